// round 1
// baseline (speedup 1.0000x reference)
#include <cuda_runtime.h>
#include <cuda_bf16.h>

// Problem shapes (fixed by setup_inputs): N=4, Cin=4, Cout=4, K=5, H=W=128.
// Inputs: d_in[0] = log_belief f32 [N,Cin,H,W]  (262144)
//         d_in[1] = log_kernel f32 [N,Cin,Cout*K*K,H,W] (26214400)
//         d_in[2] = K (int32 scalar, ignored; hardcoded 5)
// Output: f32 [N,Cout,H,W] (262144)
//
// Gather formulation:
// out[n,cout,oy,ox] = log sum_{cin,ky,kx, in-bounds} exp(
//     belief[n,cin,oy+2-ky,ox+2-kx] + kernel[n,cin,cout*25+ky*5+kx, oy+2-ky, ox+2-kx])

#define NN    4
#define CIN   4
#define COUT  4
#define KSZ   5
#define HH    128
#define WW    128
#define KK    (KSZ*KSZ)        // 25
#define SHIFT 12.0f

__global__ __launch_bounds__(WW, 4)
void prop_belief_kernel(const float* __restrict__ bel,
                        const float* __restrict__ ker,
                        float* __restrict__ out) {
    const int oy   = blockIdx.x;   // output row
    const int cout = blockIdx.y;
    const int n    = blockIdx.z;
    const int x    = threadIdx.x;  // output column

    // Stage the 5 belief rows (per cin) this output row needs.
    // sb[(cin*KSZ + ky)*WW + xs] = belief[n,cin, oy+2-ky, xs] + SHIFT
    __shared__ float sb[CIN * KSZ * WW];
    for (int i = threadIdx.x; i < CIN * KSZ * WW; i += blockDim.x) {
        const int cin = i / (KSZ * WW);
        const int ky  = (i / WW) % KSZ;
        const int xs  = i % WW;
        const int ys  = oy + 2 - ky;
        float v = 0.0f;  // unused when ys out of range (guarded below)
        if (ys >= 0 && ys < HH)
            v = __ldg(bel + ((size_t)(n * CIN + cin) * HH + ys) * WW + xs) + SHIFT;
        sb[i] = v;
    }
    __syncthreads();

    const size_t plane = (size_t)HH * WW;  // one channel plane of log_kernel

    float s0 = 0.0f, s1 = 0.0f;  // two accumulators to shorten the FADD chain

    #pragma unroll
    for (int cin = 0; cin < CIN; ++cin) {
        // base of channel block [cout*25 .. cout*25+24] for this (n,cin)
        const float* kbase = ker +
            ((size_t)(n * CIN + cin) * (COUT * KK) + (size_t)cout * KK) * plane;

        #pragma unroll
        for (int ky = 0; ky < KSZ; ++ky) {
            const int ys = oy + 2 - ky;
            if (ys < 0 || ys >= HH) continue;   // uniform per block -> cheap branch

            const float* krow = kbase + (size_t)(ky * KSZ) * plane + (size_t)ys * WW;
            const float* brow = sb + (cin * KSZ + ky) * WW;

            #pragma unroll
            for (int kx = 0; kx < KSZ; ++kx) {
                const int xs = x + 2 - kx;
                if (xs >= 0 && xs < WW) {
                    // contiguous, row-aligned 512B segment per (cin,ky,kx) tap
                    const float kv = __ldg(krow + (size_t)kx * plane + xs);
                    const float v  = brow[xs] + kv;       // belief already has +SHIFT
                    if (kx & 1) s1 += __expf(v);
                    else        s0 += __expf(v);
                }
            }
        }
    }

    out[((size_t)(n * COUT + cout) * HH + oy) * WW + x] = __logf(s0 + s1) - SHIFT;
}

extern "C" void kernel_launch(void* const* d_in, const int* in_sizes, int n_in,
                              void* d_out, int out_size) {
    const float* bel = (const float*)d_in[0];
    const float* ker = (const float*)d_in[1];
    float* out = (float*)d_out;

    dim3 grid(HH, COUT, NN);   // (oy, cout, n) = (128, 4, 4) = 2048 blocks
    dim3 block(WW);            // 128 threads: one per output column
    prop_belief_kernel<<<grid, block>>>(bel, ker, out);
}

// round 2
// speedup vs baseline: 1.7486x; 1.7486x over previous
#include <cuda_runtime.h>
#include <cuda_bf16.h>

// Problem shapes (fixed): N=4, Cin=4, Cout=4, K=5, H=W=128.
// Inputs: d_in[0] = log_belief f32 [N,Cin,H,W]        (262144)
//         d_in[1] = log_kernel f32 [N,Cin,Cout*25,H,W] (26214400)
//         d_in[2] = K (int scalar, ignored)
// Output: f32 [N,Cout,H,W]
//
// Gather form:
// out[n,cout,oy,ox] = log sum_{cin,ky,kx in-bounds} exp(
//    bel[n,cin,oy+2-ky,ox+2-kx] + ker[n,cin,cout*25+ky*5+kx, oy+2-ky, ox+2-kx])
//
// Branch-free: belief staged in shared with -1e30 halo (and -1e30 rows for
// invalid ys); kernel loaded unconditionally at clamped-ys addresses. Any
// out-of-range tap gets bv = -1e30 -> exp() == 0. All such kernel addresses
// stay inside the 26.2M-element tensor (verified for all corner cases), and
// every value there is finite, so no NaN/Inf contamination.

#define NN    4
#define CIN   4
#define COUT  4
#define KSZ   5
#define HH    128
#define WW    128
#define KK    (KSZ*KSZ)          // 25
#define PLANE (HH*WW)            // 16384
#define SHIFT 12.0f
#define NEGBIG 1e30f
#define WEXT  132                // 128 + 2-halo each side
#define NG    (CIN*KSZ)          // 20 tap groups of 5 LDGs each

__global__ __launch_bounds__(WW, 6)
void prop_belief_kernel(const float* __restrict__ bel,
                        const float* __restrict__ ker,
                        float* __restrict__ out) {
    const int oy   = blockIdx.x;
    const int cout = blockIdx.y;
    const int n    = blockIdx.z;
    const int x    = threadIdx.x;

    // Haloed belief rows: sb[g][i], g = cin*5+ky, i = xs+2.
    __shared__ float sb[NG][WEXT];

    #pragma unroll
    for (int g = 0; g < NG; ++g) {
        const int cin = g / KSZ, ky = g % KSZ;
        const int ys  = oy + 2 - ky;
        const bool yok = (ys >= 0) && (ys < HH);
        const float* brow = bel + ((size_t)(n * CIN + cin) * HH + (yok ? ys : 0)) * WW;
        for (int i = threadIdx.x; i < WEXT; i += WW) {
            const int xs = i - 2;
            float v = -NEGBIG;
            if (yok && xs >= 0 && xs < WW) v = __ldg(brow + xs) + SHIFT;
            sb[g][i] = v;
        }
    }
    __syncthreads();

    // Per-group kernel row base (ys clamped; validity handled by sb halo).
    // Tap kx reads  rowbase + kx*PLANE + (x + 2 - kx)  =  p + kx*(PLANE-1).
    auto rowptr = [&](int g) -> const float* {
        const int cin = g / KSZ, ky = g % KSZ;
        int ys = oy + 2 - ky;
        ys = ys < 0 ? 0 : (ys > HH - 1 ? HH - 1 : ys);
        return ker + ((size_t)(n * CIN + cin) * (COUT * KK)
                      + (size_t)cout * KK + (size_t)(ky * KSZ)) * PLANE
                   + (size_t)ys * WW + x + 2;
    };

    // Register ring buffer: prefetch distance = 2 groups (10 LDGs in flight).
    float kv[3][KSZ];

    #pragma unroll
    for (int s = 0; s < 2; ++s) {
        const float* p = rowptr(s);
        #pragma unroll
        for (int kx = 0; kx < KSZ; ++kx)
            kv[s][kx] = __ldg(p + kx * (PLANE - 1));
    }

    float a0 = 0.0f, a1 = 0.0f;

    #pragma unroll
    for (int g = 0; g < NG; ++g) {
        // Issue next group's 5 loads before consuming this group.
        if (g + 2 < NG) {
            const float* p = rowptr(g + 2);
            #pragma unroll
            for (int kx = 0; kx < KSZ; ++kx)
                kv[(g + 2) % 3][kx] = __ldg(p + kx * (PLANE - 1));
        }
        #pragma unroll
        for (int kx = 0; kx < KSZ; ++kx) {
            const float v = sb[g][x + 4 - kx] + kv[g % 3][kx];
            if (kx & 1) a1 += __expf(v);
            else        a0 += __expf(v);
        }
    }

    out[((size_t)(n * COUT + cout) * HH + oy) * WW + x] = __logf(a0 + a1) - SHIFT;
}

extern "C" void kernel_launch(void* const* d_in, const int* in_sizes, int n_in,
                              void* d_out, int out_size) {
    const float* bel = (const float*)d_in[0];
    const float* ker = (const float*)d_in[1];
    float* out = (float*)d_out;

    dim3 grid(HH, COUT, NN);   // (oy, cout, n)
    dim3 block(WW);
    prop_belief_kernel<<<grid, block>>>(bel, ker, out);
}

// round 5
// speedup vs baseline: 2.0761x; 1.1873x over previous
#include <cuda_runtime.h>
#include <cuda_pipeline.h>

// N=4, Cin=4, Cout=4, K=5, H=W=128.
// d_in[0] = log_belief f32 [N,Cin,H,W], d_in[1] = log_kernel f32 [N,Cin,Cout*25,H,W]
// out = f32 [N,Cout,H,W]
//
// out[n,cout,oy,ox] = log sum_{cin,ky,kx in-bounds} exp(
//    bel[n,cin,oy+2-ky,ox+2-kx] + ker[n,cin,cout*25+ky*5+kx, oy+2-ky, ox+2-kx])
//
// The 100 kernel rows each block needs are streamed through a multistage
// shared-memory ring via __pipeline_memcpy_async (depth 8, 4 rows/stage).
// Bounds are branch-free: belief staged with a -1e30 halo; kernel rows
// fetched at clamped ys and read at clamped xs (the -1e30 belief zeroes
// any invalid tap through exp()). All clamped addresses stay in-tensor.

#define NN      4
#define CIN     4
#define COUT    4
#define KSZ     5
#define HH      128
#define WW      128
#define KK      25
#define PLANE   (HH*WW)
#define SHIFT   12.0f
#define NEGBIG  1e30f
#define WEXT    132
#define NG      20          // cin*5+ky groups
#define NSTAGES 25          // 100 rows / 4 rows per stage
#define DPTH    8           // pipeline depth (stages in flight)
#define NSLOT   (DPTH+1)    // +1 slot -> one barrier per stage is safe

__global__ __launch_bounds__(128, 6)
void prop_belief_kernel(const float* __restrict__ bel,
                        const float* __restrict__ ker,
                        float* __restrict__ out) {
    const int oy   = blockIdx.x;
    const int cout = blockIdx.y;
    const int n    = blockIdx.z;
    const int x    = threadIdx.x;        // output column
    const int w    = threadIdx.x >> 5;   // warp id: which row of the stage
    const int lane = threadIdx.x & 31;

    __shared__ float ring[NSLOT][4][WW]; // 4 kernel rows per stage
    __shared__ float sb[NG][WEXT];       // haloed belief rows

    // Row r (0..99): cin = r/25, pk = r%25 (= ky*5+kx).
    // Plane index in ker = n*400 + cout*25 + cin*100 + pk.  (max 1599 < 1600)
    const int pbase = n * (CIN * COUT * KK) + cout * KK;

    // ---- issue this warp's cp.async row for stage s (16B per lane) ----
    auto issue_row = [&](int s) {
        const int r   = 4 * s + w;
        const int cin = r / 25;
        const int pk  = r - cin * 25;
        const int ky  = pk / 5;
        int ys = oy + 2 - ky;
        ys = ys < 0 ? 0 : (ys > HH - 1 ? HH - 1 : ys);
        const float* src = ker + ((size_t)(pbase + cin * 100 + pk)) * PLANE
                               + (size_t)ys * WW + lane * 4;
        __pipeline_memcpy_async(&ring[s % NSLOT][w][lane * 4], src, 16);
    };

    // ---- prologue: fill the pipe ----
    #pragma unroll
    for (int s = 0; s < DPTH; ++s) {
        issue_row(s);
        __pipeline_commit();
    }

    // ---- stage belief rows (overlapped with the async prologue) ----
    #pragma unroll 1
    for (int i = threadIdx.x; i < NG * WEXT; i += 128) {
        const int g  = i / WEXT;
        const int xi = i - g * WEXT;
        const int cin = g / KSZ, ky = g % KSZ;
        const int ys = oy + 2 - ky;
        const int xs = xi - 2;
        float v = -NEGBIG;
        if (ys >= 0 && ys < HH && xs >= 0 && xs < WW)
            v = __ldg(bel + ((size_t)(n * CIN + cin) * HH + ys) * WW + xs) + SHIFT;
        sb[g][xi] = v;
    }
    __syncthreads();

    float a0 = 0.f, a1 = 0.f, a2 = 0.f, a3 = 0.f;

    // ---- main pipeline ----
    #pragma unroll
    for (int s = 0; s < NSTAGES; ++s) {
        __pipeline_wait_prior(DPTH - 1);   // stage s's groups complete
        __syncthreads();                   // visible to all; frees old slot

        const float* rows = &ring[s % NSLOT][0][0];

        #pragma unroll
        for (int j = 0; j < 4; ++j) {
            const int r   = 4 * s + j;
            const int cin = r / 25;
            const int pk  = r - cin * 25;
            const int ky  = pk / 5;
            const int kx  = pk - ky * 5;
            const int g   = cin * KSZ + ky;

            const int xs  = x + 2 - kx;
            const int xsc = xs < 0 ? 0 : (xs > WW - 1 ? WW - 1 : xs);
            const float kv = rows[j * WW + xsc];
            const float bv = sb[g][x + 4 - kx];   // -1e30 when tap invalid
            const float e  = __expf(bv + kv);
            if      (j == 0) a0 += e;
            else if (j == 1) a1 += e;
            else if (j == 2) a2 += e;
            else             a3 += e;
        }

        if (s + DPTH < NSTAGES) issue_row(s + DPTH);
        __pipeline_commit();               // keep group count uniform
    }

    out[((size_t)(n * COUT + cout) * HH + oy) * WW + x] =
        __logf((a0 + a1) + (a2 + a3)) - SHIFT;
}

extern "C" void kernel_launch(void* const* d_in, const int* in_sizes, int n_in,
                              void* d_out, int out_size) {
    const float* bel = (const float*)d_in[0];
    const float* ker = (const float*)d_in[1];
    float* out = (float*)d_out;

    dim3 grid(HH, COUT, NN);   // (oy, cout, n)
    dim3 block(128);
    prop_belief_kernel<<<grid, block>>>(bel, ker, out);
}